// round 14
// baseline (speedup 1.0000x reference)
#include <cuda_runtime.h>
#include <cuda_fp16.h>
#include <math.h>

// MoE router via mma.sync m16n8k16 fp16 2-plane split (3 f32-acc products):
//   logits = x[T,4096] @ W[64,4096]^T; x = xh+xm (exact residual),
//   W*64 = Wh+Wm (exact scale, undone at softmax).
// R14: BOTH operands pre-split to interleaved fp16 planes in smem via
// write-ahead double buffering (LDG->split->STS one chunk ahead). Inner loop
// is pure LDS+mma. No cp.async -> ONE syncthreads per chunk.

#define HID  4096
#define NE   64
#define TM   128
#define KC   32
#define KSPL 4
#define KPER (HID / KSPL)         // 1024
#define NCH  (KPER / KC)          // 32
#define NT   256
#define ROWB 160                  // row stride bytes (20 uint2), A and B alike
#define XBUFB (TM * ROWB)         // 20480 per x buffer
#define WOFF  (2 * XBUFB)        // 40960
#define WBUFB (NE * ROWB)         // 10240 per W buffer
#define SMEM_BYTES (WOFF + 2 * WBUFB)   // 61440 -> 2 CTAs/SM easily

static __device__ float g_partial[KSPL * 8192 * NE];   // 8 MB

__device__ __forceinline__ unsigned smem_u32(const void* p) {
    unsigned r;
    asm("{ .reg .u64 t; cvta.to.shared.u64 t, %1; cvt.u32.u64 %0, t; }"
        : "=r"(r) : "l"(p));
    return r;
}
__device__ __forceinline__ void valsplit(float2 v, unsigned& h, unsigned& m) {
    __half2 hh = __float22half2_rn(v);
    float2 hb = __half22float2(hh);
    __half2 mm = __float22half2_rn(make_float2(v.x - hb.x, v.y - hb.y));
    h = *(unsigned*)&hh;
    m = *(unsigned*)&mm;
}
__device__ __forceinline__ void mma_f16(float* c, const unsigned* a, const unsigned* b) {
    asm volatile(
        "mma.sync.aligned.m16n8k16.row.col.f32.f16.f16.f32 "
        "{%0,%1,%2,%3},{%4,%5,%6,%7},{%8,%9},{%0,%1,%2,%3};"
        : "+f"(c[0]), "+f"(c[1]), "+f"(c[2]), "+f"(c[3])
        : "r"(a[0]), "r"(a[1]), "r"(a[2]), "r"(a[3]), "r"(b[0]), "r"(b[1]));
}
__device__ __forceinline__ void sts128(unsigned addr, unsigned a, unsigned b,
                                       unsigned cc, unsigned d) {
    asm volatile("st.shared.v4.b32 [%0], {%1,%2,%3,%4};"
                 :: "r"(addr), "r"(a), "r"(b), "r"(cc), "r"(d));
}
// split a float4 (optionally pre-scaled) and store interleaved {h2,m2,h2,m2}
__device__ __forceinline__ void stage4(float4 v, float sc, unsigned addr) {
    unsigned h0, m0, h1, m1;
    valsplit(make_float2(v.x * sc, v.y * sc), h0, m0);
    valsplit(make_float2(v.z * sc, v.w * sc), h1, m1);
    sts128(addr, h0, m0, h1, m1);
}

// -------- kernel 1: split-K(4) GEMM, all-presplit smem, 1 sync/chunk --------
__global__ __launch_bounds__(NT, 2) void moe_gemm_kernel(
    const float* __restrict__ x, const float* __restrict__ w, int T)
{
    extern __shared__ char smc[];
    const unsigned sbase = smem_u32(smc);
    const int tid = threadIdx.x;
    const int wid = tid >> 5;
    const int lane = tid & 31;
    const int tok0 = blockIdx.x * TM;
    const int ks = blockIdx.y;
    const int kbase = ks * KPER;

    // x: 4 float4/thread/chunk; u = it*NT+tid -> row=u>>3, c4=u&7
    const float4* xsrc[4]; unsigned xsts[4];
    #pragma unroll
    for (int it = 0; it < 4; it++) {
        int u = it * NT + tid, row = u >> 3, c4 = u & 7;
        xsrc[it] = (const float4*)(x + (size_t)(tok0 + row) * HID + kbase + c4 * 4);
        xsts[it] = sbase + (unsigned)(row * ROWB + c4 * 16);
    }
    // W: 2 float4/thread/chunk
    const float4* wsrc[2]; unsigned wsts[2];
    #pragma unroll
    for (int q = 0; q < 2; q++) {
        int u = q * NT + tid, row = u >> 3, c4 = u & 7;
        wsrc[q] = (const float4*)(w + (size_t)row * HID + kbase + c4 * 4);
        wsts[q] = sbase + WOFF + (unsigned)(row * ROWB + c4 * 16);
    }

    float acc[8][4];
    #pragma unroll
    for (int nt = 0; nt < 8; nt++)
        #pragma unroll
        for (int i = 0; i < 4; i++) acc[nt][i] = 0.f;

    // prologue: chunk 0 -> buffers 0; prefetch chunk 1 into regs
    float4 xr[4], wr[2];
    #pragma unroll
    for (int it = 0; it < 4; it++) xr[it] = xsrc[it][0];
    #pragma unroll
    for (int q = 0; q < 2; q++) wr[q] = wsrc[q][0];
    #pragma unroll
    for (int it = 0; it < 4; it++) stage4(xr[it], 1.f, xsts[it]);
    #pragma unroll
    for (int q = 0; q < 2; q++) stage4(wr[q], 64.f, wsts[q]);
    #pragma unroll
    for (int it = 0; it < 4; it++) xr[it] = xsrc[it][8];
    #pragma unroll
    for (int q = 0; q < 2; q++) wr[q] = wsrc[q][8];

    const int eq = lane >> 2;           // groupID 0..7
    const int kq = lane & 3;            // threadInGroup 0..3
    const int rbase = wid * 16 + eq;

    #pragma unroll 1
    for (int c = 0; c < NCH; c++) {
        __syncthreads();                // compute c-1 done; buf (c+1)&1 free;
                                        // buf c&1 (staged in iter c-1) visible
        if (c + 1 < NCH) {
            unsigned xo = (unsigned)(((c + 1) & 1) * XBUFB);
            unsigned wo = (unsigned)(((c + 1) & 1) * WBUFB);
            #pragma unroll
            for (int it = 0; it < 4; it++) stage4(xr[it], 1.f, xsts[it] + xo);
            #pragma unroll
            for (int q = 0; q < 2; q++) stage4(wr[q], 64.f, wsts[q] + wo);
            if (c + 2 < NCH) {
                #pragma unroll
                for (int it = 0; it < 4; it++) xr[it] = xsrc[it][(c + 2) * 8];
                #pragma unroll
                for (int q = 0; q < 2; q++) wr[q] = wsrc[q][(c + 2) * 8];
            }
        }

        const uint2* ax = (const uint2*)(smc + (c & 1) * XBUFB);
        const uint2* bw = (const uint2*)(smc + WOFF + (c & 1) * WBUFB);

        #pragma unroll
        for (int sl = 0; sl < 2; sl++) {        // two k16 steps per chunk
            const int base = sl * 8 + kq;
            uint2 a0 = ax[rbase * 20 + base];
            uint2 a1 = ax[(rbase + 8) * 20 + base];
            uint2 a2 = ax[rbase * 20 + base + 4];
            uint2 a3 = ax[(rbase + 8) * 20 + base + 4];
            unsigned Ah[4] = {a0.x, a1.x, a2.x, a3.x};
            unsigned Am[4] = {a0.y, a1.y, a2.y, a3.y};
            unsigned Bh[8][2], Bm[8][2];
            #pragma unroll
            for (int nt = 0; nt < 8; nt++) {
                int e = nt * 8 + eq;
                uint2 t0 = bw[e * 20 + base];
                uint2 t1 = bw[e * 20 + base + 4];
                Bh[nt][0] = t0.x; Bm[nt][0] = t0.y;
                Bh[nt][1] = t1.x; Bm[nt][1] = t1.y;
            }
            #pragma unroll
            for (int nt = 0; nt < 8; nt++) {
                mma_f16(acc[nt], Ah, Bh[nt]);
                mma_f16(acc[nt], Ah, Bm[nt]);
                mma_f16(acc[nt], Am, Bh[nt]);
            }
        }
    }

    // ---- write fp32 partials (x64-scaled; top2 unscales at softmax)
    {
        int row = tok0 + rbase;
        float* d0 = g_partial + ((size_t)ks * T + row) * NE;
        float* d8 = d0 + (size_t)8 * NE;
        #pragma unroll
        for (int nt = 0; nt < 8; nt++) {
            int col = nt * 8 + kq * 2;
            *(float2*)(d0 + col) = make_float2(acc[nt][0], acc[nt][1]);
            *(float2*)(d8 + col) = make_float2(acc[nt][2], acc[nt][3]);
        }
    }
}

// ---------------- kernel 2: reduce + top-2 + softmax (R12 form) ------------
__global__ __launch_bounds__(256) void moe_top2_kernel(float* __restrict__ out,
                                                       int T, int write_map) {
    const int lane = threadIdx.x & 31;
    const int t = blockIdx.x * 8 + (threadIdx.x >> 5);
    const int c0 = lane * 2, c1 = lane * 2 + 1;

    float2 s = make_float2(0.f, 0.f);
    #pragma unroll
    for (int ksi = 0; ksi < KSPL; ksi++) {
        float2 v = *(const float2*)(g_partial + ((size_t)ksi * T + t) * NE + c0);
        s.x += v.x; s.y += v.y;
    }
    float v1, v2; int i1, i2;
    if (s.y > s.x) { v1 = s.y; i1 = c1; v2 = s.x; i2 = c0; }
    else           { v1 = s.x; i1 = c0; v2 = s.y; i2 = c1; }

    #pragma unroll
    for (int sh = 16; sh >= 1; sh >>= 1) {
        float ov1 = __shfl_xor_sync(0xffffffffu, v1, sh);
        int   oi1 = __shfl_xor_sync(0xffffffffu, i1, sh);
        float ov2 = __shfl_xor_sync(0xffffffffu, v2, sh);
        int   oi2 = __shfl_xor_sync(0xffffffffu, i2, sh);
        bool ob = (ov1 > v1) || (ov1 == v1 && oi1 < i1);   // jax tie-break
        float nv1 = ob ? ov1 : v1;  int ni1 = ob ? oi1 : i1;
        float cv  = ob ? v1  : ov1; int ci  = ob ? i1  : oi1;
        float sv  = ob ? ov2 : v2;  int si  = ob ? oi2 : i2;
        bool b2 = (cv > sv) || (cv == sv && ci < si);
        v2 = b2 ? cv : sv; i2 = b2 ? ci : si;
        v1 = nv1; i1 = ni1;
    }
    // logits carry the exact x64 W scale; undo on the difference (exact)
    float ex = expf((v2 - v1) * 0.015625f);   // <= 1, stable
    float inv = 1.f / (1.f + ex);
    float pp1 = inv, pp2 = ex * inv;

    float2 po;
    po.x = (c0 == i1) ? pp1 : ((c0 == i2) ? pp2 : 0.f);
    po.y = (c1 == i1) ? pp1 : ((c1 == i2) ? pp2 : 0.f);
    *(float2*)(out + (size_t)t * NE + c0) = po;
    if (write_map) {
        float2 mo;
        mo.x = (c0 == i1 || c0 == i2) ? 1.f : 0.f;
        mo.y = (c1 == i1 || c1 == i2) ? 1.f : 0.f;
        *(float2*)(out + (size_t)T * NE + (size_t)t * NE + c0) = mo;
    }
}

extern "C" void kernel_launch(void* const* d_in, const int* in_sizes, int n_in,
                              void* d_out, int out_size) {
    const float* x = (const float*)d_in[0];   // [2048,4,4096] fp32
    const float* w = (const float*)d_in[1];   // [64,4096] fp32
    float* out = (float*)d_out;
    int T = in_sizes[0] / HID;                // 8192
    int write_map = (out_size >= 2 * T * NE) ? 1 : 0;

    static int smem_set = 0;
    if (!smem_set) {
        cudaFuncSetAttribute(moe_gemm_kernel,
                             cudaFuncAttributeMaxDynamicSharedMemorySize, SMEM_BYTES);
        smem_set = 1;
    }
    dim3 grid(T / TM, KSPL);
    moe_gemm_kernel<<<grid, NT, SMEM_BYTES>>>(x, w, T);
    moe_top2_kernel<<<T / 8, 256>>>(out, T, write_map);
}